// round 1
// baseline (speedup 1.0000x reference)
#include <cuda_runtime.h>
#include <cuda_bf16.h>
#include <math.h>

// Problem dims
#define LL 256
#define BB 256
#define VV 50000
#define EE 300
#define HH 256
#define TT 17
#define G4H 1024   // 4*H
#define H2  512    // 2*H
#define MM  (LL*BB)  // 65536

// ---------------- scratch (device globals; no allocation allowed) ----------------
__device__ float g_xproj[2][(size_t)MM * G4H];  // 2 x 256MB
__device__ float g_h[2][(size_t)MM * HH];       // 2 x 64MB  (layout [t][b][h])
__device__ float g_c[2][BB * HH];               // current cell state per dir
__device__ float g_em[(size_t)MM * TT];         // emissions [l*B+b][T]
__device__ float g_WihT[2][EE * G4H];           // [k][n]
__device__ float g_WhhT[2][HH * G4H];           // [k][n]
__device__ float g_bias[2][G4H];                // b_ih + b_hh
__device__ float g_score[BB];
__device__ float g_logZ[BB];

__device__ __forceinline__ float sigmoidf_(float x) { return 1.0f / (1.0f + expf(-x)); }

// ---------------- prep: transpose weights, sum biases ----------------
__global__ void prep_kernel(const float* __restrict__ w_ih_f, const float* __restrict__ w_hh_f,
                            const float* __restrict__ b_ih_f, const float* __restrict__ b_hh_f,
                            const float* __restrict__ w_ih_b, const float* __restrict__ w_hh_b,
                            const float* __restrict__ b_ih_b, const float* __restrict__ b_hh_b) {
    int idx = blockIdx.x * blockDim.x + threadIdx.x;
    int stride = gridDim.x * blockDim.x;
    for (int i = idx; i < EE * G4H; i += stride) {
        int k = i / G4H, n = i % G4H;
        g_WihT[0][i] = w_ih_f[n * EE + k];
        g_WihT[1][i] = w_ih_b[n * EE + k];
    }
    for (int i = idx; i < HH * G4H; i += stride) {
        int k = i / G4H, n = i % G4H;
        g_WhhT[0][i] = w_hh_f[n * HH + k];
        g_WhhT[1][i] = w_hh_b[n * HH + k];
    }
    for (int i = idx; i < G4H; i += stride) {
        g_bias[0][i] = b_ih_f[i] + b_hh_f[i];
        g_bias[1][i] = b_ih_b[i] + b_hh_b[i];
    }
}

// ---------------- xproj GEMM: out[m][n] = sum_k embed[words[m]][k]*WihT[k][n] + bias[n]
// BM=128, BN=64, BK=16, 256 threads, micro-tile 8x4. grid (16, 512, 2)
__global__ void xproj_kernel(const int* __restrict__ words, const float* __restrict__ embed) {
    __shared__ float As[16][128];
    __shared__ float Bs[16][64];
    int dir = blockIdx.z;
    const float* __restrict__ WT = g_WihT[dir];
    const float* __restrict__ bias = g_bias[dir];
    float* __restrict__ out = g_xproj[dir];

    int bm = blockIdx.y * 128;
    int bn = blockIdx.x * 64;
    int tid = threadIdx.x;
    int tx = tid & 15;        // 0..15  -> cols tx*4
    int ty = tid >> 4;        // 0..15  -> rows ty*8

    // A loader: row lm = tid/2, k-half = tid%2 (8 k's each)
    int lm = tid >> 1;
    int khalf = tid & 1;
    int word = words[bm + lm];
    const float* arow = embed + (size_t)word * EE;

    // B loader: n = tid%64, kb = tid/64 (4 k's each)
    int bln = tid & 63;
    int bkb = tid >> 6;

    float acc[8][4];
    #pragma unroll
    for (int i = 0; i < 8; i++)
        #pragma unroll
        for (int j = 0; j < 4; j++) acc[i][j] = 0.0f;

    const int KT = (EE + 15) / 16; // 19
    for (int kt = 0; kt < KT; kt++) {
        int k0 = kt * 16;
        #pragma unroll
        for (int u = 0; u < 8; u++) {
            int k = k0 + khalf * 8 + u;
            As[khalf * 8 + u][lm] = (k < EE) ? arow[k] : 0.0f;
        }
        #pragma unroll
        for (int u = 0; u < 4; u++) {
            int k = bkb * 4 + u;
            int kg = k0 + k;
            Bs[k][bln] = (kg < EE) ? WT[(size_t)kg * G4H + bn + bln] : 0.0f;
        }
        __syncthreads();
        #pragma unroll
        for (int kk = 0; kk < 16; kk++) {
            float a[8], b[4];
            float4 a0 = *reinterpret_cast<const float4*>(&As[kk][ty * 8]);
            float4 a1 = *reinterpret_cast<const float4*>(&As[kk][ty * 8 + 4]);
            a[0]=a0.x; a[1]=a0.y; a[2]=a0.z; a[3]=a0.w;
            a[4]=a1.x; a[5]=a1.y; a[6]=a1.z; a[7]=a1.w;
            float4 b0 = *reinterpret_cast<const float4*>(&Bs[kk][tx * 4]);
            b[0]=b0.x; b[1]=b0.y; b[2]=b0.z; b[3]=b0.w;
            #pragma unroll
            for (int i = 0; i < 8; i++)
                #pragma unroll
                for (int j = 0; j < 4; j++) acc[i][j] += a[i] * b[j];
        }
        __syncthreads();
    }
    // epilogue
    int ncol = bn + tx * 4;
    float4 bv = *reinterpret_cast<const float4*>(&bias[ncol]);
    #pragma unroll
    for (int i = 0; i < 8; i++) {
        int row = bm + ty * 8 + i;
        float4 v;
        v.x = acc[i][0] + bv.x; v.y = acc[i][1] + bv.y;
        v.z = acc[i][2] + bv.z; v.w = acc[i][3] + bv.w;
        *reinterpret_cast<float4*>(&out[(size_t)row * G4H + ncol]) = v;
    }
}

// ---------------- LSTM step: gates = h_prev @ WhhT + xproj; pointwise -> h,c
// grid (64, 2): x = mt*16 + ht (mt 0..3 row-tile of 64 batch rows, ht 0..15 h-tile of 16)
// block 256 threads; 64 rows x 64 gate-cols (4 gates x 16 h), micro 4x4.
__global__ void lstm_step_kernel(int s) {
    __shared__ float As[16][64];
    __shared__ float Bs[16][64];
    __shared__ float gsm[64][68];

    int dir = blockIdx.y;
    int t = dir ? (LL - 1 - s) : s;
    int mt = blockIdx.x >> 4;
    int ht = blockIdx.x & 15;
    int bm = mt * 64;
    int h0 = ht * 16;

    int tid = threadIdx.x;
    int tx = tid & 15;   // col group (4 cols)
    int ty = tid >> 4;   // row group (4 rows)
    int g  = tx >> 2;            // gate 0..3 for this thread's cols
    int jj = (tx & 3) * 4;       // h-offset within tile for col j=0

    const float* __restrict__ xp = &g_xproj[dir][(size_t)(t * BB) * G4H];

    float acc[4][4];
    #pragma unroll
    for (int i = 0; i < 4; i++) {
        int row = bm + ty * 4 + i;
        int n = g * HH + h0 + jj;
        float4 v = *reinterpret_cast<const float4*>(&xp[(size_t)row * G4H + n]);
        acc[i][0] = v.x; acc[i][1] = v.y; acc[i][2] = v.z; acc[i][3] = v.w;
    }

    if (s > 0) {
        int tprev = dir ? (t + 1) : (t - 1);
        const float* __restrict__ hprev = &g_h[dir][(size_t)tprev * BB * HH];
        const float* __restrict__ WT = g_WhhT[dir];
        int alm = tid >> 2;      // A loader row 0..63
        int akq = tid & 3;       // k quarter
        int bln = tid & 63;      // B loader col 0..63
        int bkb = tid >> 6;      // B loader k group
        int bn_g = (bln >> 4) * HH + h0 + (bln & 15);  // global n for this B col

        for (int kt = 0; kt < 16; kt++) {
            int k0 = kt * 16;
            float4 av = *reinterpret_cast<const float4*>(&hprev[(size_t)(bm + alm) * HH + k0 + akq * 4]);
            As[akq * 4 + 0][alm] = av.x;
            As[akq * 4 + 1][alm] = av.y;
            As[akq * 4 + 2][alm] = av.z;
            As[akq * 4 + 3][alm] = av.w;
            #pragma unroll
            for (int u = 0; u < 4; u++) {
                int k = bkb * 4 + u;
                Bs[k][bln] = WT[(size_t)(k0 + k) * G4H + bn_g];
            }
            __syncthreads();
            #pragma unroll
            for (int kk = 0; kk < 16; kk++) {
                float4 a0 = *reinterpret_cast<const float4*>(&As[kk][ty * 4]);
                float4 b0 = *reinterpret_cast<const float4*>(&Bs[kk][tx * 4]);
                float a[4] = {a0.x, a0.y, a0.z, a0.w};
                float b[4] = {b0.x, b0.y, b0.z, b0.w};
                #pragma unroll
                for (int i = 0; i < 4; i++)
                    #pragma unroll
                    for (int j = 0; j < 4; j++) acc[i][j] += a[i] * b[j];
            }
            __syncthreads();
        }
    }

    // stash gates in smem so each thread can see all 4 gates of its (b,h)
    #pragma unroll
    for (int i = 0; i < 4; i++)
        #pragma unroll
        for (int j = 0; j < 4; j++) gsm[ty * 4 + i][tx * 4 + j] = acc[i][j];
    __syncthreads();

    // pointwise LSTM: 1024 (row, h) pairs, 4 per thread
    #pragma unroll
    for (int q = 0; q < 4; q++) {
        int p = tid + q * 256;
        int row = p >> 4;
        int j2 = p & 15;
        float ig = sigmoidf_(gsm[row][j2]);
        float fg = sigmoidf_(gsm[row][16 + j2]);
        float gg = tanhf(gsm[row][32 + j2]);
        float og = sigmoidf_(gsm[row][48 + j2]);
        int b = bm + row;
        int h = h0 + j2;
        float cold = (s == 0) ? 0.0f : g_c[dir][b * HH + h];
        float cn = fg * cold + ig * gg;
        float hn = og * tanhf(cn);
        g_c[dir][b * HH + h] = cn;
        g_h[dir][(size_t)t * BB * HH + (size_t)b * HH + h] = hn;
    }
}

// ---------------- emissions: em[m][t] = [h_f|h_b][m] . lin_w[t] + lin_b[t]
// one warp per m-row; block 256 threads = 8 rows; grid 8192
__global__ void emissions_kernel(const float* __restrict__ lin_w, const float* __restrict__ lin_b) {
    __shared__ float ws[TT * H2];
    __shared__ float bs[TT];
    int tid = threadIdx.x;
    for (int i = tid; i < TT * H2; i += 256) ws[i] = lin_w[i];
    if (tid < TT) bs[tid] = lin_b[tid];
    __syncthreads();
    int warp = tid >> 5, lane = tid & 31;
    int m = blockIdx.x * 8 + warp;
    const float* hf = &g_h[0][(size_t)m * HH];
    const float* hb = &g_h[1][(size_t)m * HH];
    float xv[16];
    #pragma unroll
    for (int i = 0; i < 8; i++) xv[i] = hf[i * 32 + lane];
    #pragma unroll
    for (int i = 0; i < 8; i++) xv[8 + i] = hb[i * 32 + lane];
    for (int t = 0; t < TT; t++) {
        float p = 0.0f;
        #pragma unroll
        for (int i = 0; i < 16; i++) p += xv[i] * ws[t * H2 + i * 32 + lane];
        #pragma unroll
        for (int o = 16; o > 0; o >>= 1) p += __shfl_down_sync(0xffffffffu, p, o);
        if (lane == 0) g_em[(size_t)m * TT + t] = p + bs[t];
    }
}

// ---------------- CRF gold-path score: one warp per batch element
__global__ void score_kernel(const int* __restrict__ tags, const int* __restrict__ mask_,
                             const float* __restrict__ start_trans, const float* __restrict__ end_trans,
                             const float* __restrict__ trans) {
    int warp = threadIdx.x >> 5, lane = threadIdx.x & 31;
    int b = blockIdx.x * 8 + warp;
    float sc = 0.0f;
    int mcount = 0;
    for (int t = lane; t < LL; t += 32) {
        int mk = mask_[t * BB + b];
        mcount += mk;
        if (t >= 1 && mk) {
            int tp = tags[(t - 1) * BB + b];
            int tt = tags[t * BB + b];
            sc += trans[tp * TT + tt] + g_em[((size_t)t * BB + b) * TT + tt];
        }
    }
    #pragma unroll
    for (int o = 16; o > 0; o >>= 1) {
        sc += __shfl_down_sync(0xffffffffu, sc, o);
        mcount += __shfl_down_sync(0xffffffffu, mcount, o);
    }
    if (lane == 0) {
        int t0 = tags[b];
        sc += start_trans[t0] + g_em[(size_t)b * TT + t0];
        int lt = tags[(mcount - 1) * BB + b];
        sc += end_trans[lt];
        g_score[b] = sc;
    }
}

// ---------------- CRF forward alpha recurrence: one warp-block per batch element
__global__ void alpha_kernel(const int* __restrict__ mask_,
                             const float* __restrict__ start_trans, const float* __restrict__ end_trans,
                             const float* __restrict__ trans) {
    int b = blockIdx.x;
    int j = threadIdx.x;
    __shared__ float tr[TT * TT];
    __shared__ float al[TT];
    for (int i = j; i < TT * TT; i += 32) tr[i] = trans[i];
    if (j < TT) al[j] = start_trans[j] + g_em[(size_t)b * TT + j];
    __syncwarp();
    for (int t = 1; t < LL; t++) {
        int mk = mask_[t * BB + b];
        float nxt = 0.0f;
        if (j < TT && mk) {
            float mx = -1e30f;
            #pragma unroll
            for (int i = 0; i < TT; i++) mx = fmaxf(mx, al[i] + tr[i * TT + j]);
            float sum = 0.0f;
            #pragma unroll
            for (int i = 0; i < TT; i++) sum += expf(al[i] + tr[i * TT + j] - mx);
            nxt = mx + logf(sum) + g_em[((size_t)t * BB + b) * TT + j];
        }
        __syncwarp();
        if (j < TT && mk) al[j] = nxt;
        __syncwarp();
    }
    if (j == 0) {
        float mx = -1e30f;
        for (int i = 0; i < TT; i++) mx = fmaxf(mx, al[i] + end_trans[i]);
        float sum = 0.0f;
        for (int i = 0; i < TT; i++) sum += expf(al[i] + end_trans[i] - mx);
        g_logZ[b] = mx + logf(sum);
    }
}

// ---------------- final: nll = sum_b (logZ - score)
__global__ void final_kernel(float* __restrict__ out) {
    __shared__ float red[256];
    int b = threadIdx.x;
    red[b] = g_logZ[b] - g_score[b];
    __syncthreads();
    for (int s = 128; s > 0; s >>= 1) {
        if (b < s) red[b] += red[b + s];
        __syncthreads();
    }
    if (b == 0) out[0] = red[0];
}

// ---------------- launch ----------------
extern "C" void kernel_launch(void* const* d_in, const int* in_sizes, int n_in,
                              void* d_out, int out_size) {
    const int*   words       = (const int*)d_in[0];
    const int*   tags        = (const int*)d_in[1];
    const int*   mask        = (const int*)d_in[2];
    const float* embed_table = (const float*)d_in[3];
    const float* w_ih_f      = (const float*)d_in[4];
    const float* w_hh_f      = (const float*)d_in[5];
    const float* b_ih_f      = (const float*)d_in[6];
    const float* b_hh_f      = (const float*)d_in[7];
    const float* w_ih_b      = (const float*)d_in[8];
    const float* w_hh_b      = (const float*)d_in[9];
    const float* b_ih_b      = (const float*)d_in[10];
    const float* b_hh_b      = (const float*)d_in[11];
    const float* lin_w       = (const float*)d_in[12];
    const float* lin_b       = (const float*)d_in[13];
    const float* start_trans = (const float*)d_in[14];
    const float* end_trans   = (const float*)d_in[15];
    const float* trans       = (const float*)d_in[16];
    float* out = (float*)d_out;

    prep_kernel<<<256, 256>>>(w_ih_f, w_hh_f, b_ih_f, b_hh_f,
                              w_ih_b, w_hh_b, b_ih_b, b_hh_b);
    xproj_kernel<<<dim3(16, 512, 2), 256>>>(words, embed_table);
    for (int s = 0; s < LL; s++) {
        lstm_step_kernel<<<dim3(64, 2), 256>>>(s);
    }
    emissions_kernel<<<8192, 256>>>(lin_w, lin_b);
    score_kernel<<<32, 256>>>(tags, mask, start_trans, end_trans, trans);
    alpha_kernel<<<256, 32>>>(mask, start_trans, end_trans, trans);
    final_kernel<<<1, 256>>>(out);
}

// round 3
// speedup vs baseline: 1.3542x; 1.3542x over previous
#include <cuda_runtime.h>
#include <math.h>

#define LL 256
#define BB 256
#define EE 300
#define KPAD 304
#define HH 256
#define TT 17
#define G4H 1024
#define H2 512
#define MM 65536

// ---------------- device scratch ----------------
__device__ float g_Xg[(size_t)MM * KPAD];            // gathered embeddings, tf32-rounded, padded
__device__ float g_WihT[2][KPAD * G4H];              // [k][n] tf32-rounded
__device__ float g_WhhT[2][HH * G4H];                // [k][n] tf32-rounded
__device__ float g_bias[2][G4H];
__device__ float g_xpt[2][(size_t)LL * G4H * BB];    // [dir][t][n][b] fp32
__device__ float g_h2[2][(size_t)LL * HH * BB];      // [dir][t][h][b] fp32
__device__ float g_hcur[2][HH * BB];                 // [dir][h][b] tf32-rounded
__device__ float g_em[(size_t)MM * TT];
__device__ float g_score[BB];
__device__ float g_logZ[BB];
__device__ unsigned g_count;

__device__ __forceinline__ float tf32r(float x) {
    unsigned r;
    asm("cvt.rna.tf32.f32 %0, %1;" : "=r"(r) : "f"(x));
    return __uint_as_float(r);
}

__device__ __forceinline__ void mma_tf32(float* c, unsigned a0, unsigned a1, unsigned a2, unsigned a3,
                                         unsigned b0, unsigned b1) {
    asm volatile("mma.sync.aligned.m16n8k8.row.col.f32.tf32.tf32.f32 "
                 "{%0,%1,%2,%3},{%4,%5,%6,%7},{%8,%9},{%0,%1,%2,%3};"
                 : "+f"(c[0]), "+f"(c[1]), "+f"(c[2]), "+f"(c[3])
                 : "r"(a0), "r"(a1), "r"(a2), "r"(a3), "r"(b0), "r"(b1));
}

__device__ __forceinline__ float sigmoidf_(float x) { return 1.0f / (1.0f + __expf(-x)); }

// ---------------- prep: transpose + tf32-round weights, biases, reset barrier ----------------
__global__ void prep_kernel(const float* __restrict__ w_ih_f, const float* __restrict__ w_hh_f,
                            const float* __restrict__ b_ih_f, const float* __restrict__ b_hh_f,
                            const float* __restrict__ w_ih_b, const float* __restrict__ w_hh_b,
                            const float* __restrict__ b_ih_b, const float* __restrict__ b_hh_b) {
    int idx = blockIdx.x * blockDim.x + threadIdx.x;
    int stride = gridDim.x * blockDim.x;
    if (idx == 0) g_count = 0u;
    for (int i = idx; i < KPAD * G4H; i += stride) {
        int k = i / G4H, n = i % G4H;
        g_WihT[0][i] = (k < EE) ? tf32r(w_ih_f[n * EE + k]) : 0.0f;
        g_WihT[1][i] = (k < EE) ? tf32r(w_ih_b[n * EE + k]) : 0.0f;
    }
    for (int i = idx; i < HH * G4H; i += stride) {
        int k = i / G4H, n = i % G4H;
        g_WhhT[0][i] = tf32r(w_hh_f[n * HH + k]);
        g_WhhT[1][i] = tf32r(w_hh_b[n * HH + k]);
    }
    for (int i = idx; i < G4H; i += stride) {
        g_bias[0][i] = b_ih_f[i] + b_hh_f[i];
        g_bias[1][i] = b_ih_b[i] + b_hh_b[i];
    }
}

// ---------------- embedding gather + tf32 round + pad ----------------
__global__ void gather_kernel(const int* __restrict__ words, const float* __restrict__ embed) {
    int idx = blockIdx.x * blockDim.x + threadIdx.x;
    const int total = MM * (KPAD / 4);
    if (idx >= total) return;
    int m = idx / (KPAD / 4);
    int c4 = idx % (KPAD / 4);
    int k = c4 * 4;
    const float* row = embed + (size_t)words[m] * EE;
    float4 v;
    v.x = (k + 0 < EE) ? tf32r(row[k + 0]) : 0.0f;
    v.y = (k + 1 < EE) ? tf32r(row[k + 1]) : 0.0f;
    v.z = (k + 2 < EE) ? tf32r(row[k + 2]) : 0.0f;
    v.w = (k + 3 < EE) ? tf32r(row[k + 3]) : 0.0f;
    *reinterpret_cast<float4*>(g_Xg + (size_t)m * KPAD + k) = v;
}

// ---------------- xproj: tf32 mma GEMM. out[t][n][b] = Xg @ WihT + bias
// block tile 128(m) x 128(n), BK=16, 256 thr = 8 warps, warp 32x64.
// grid (8, 512, 2)
#define XP_ASTR 132
__global__ void xproj_kernel() {
    extern __shared__ float sm[];
    float* Asm = sm;                    // [16][132]
    float* Bsm = sm + 16 * XP_ASTR;     // [16][132]
    int dir = blockIdx.z;
    int n0 = blockIdx.x * 128;
    int m0 = blockIdx.y * 128;
    int tid = threadIdx.x;
    int w = tid >> 5, lane = tid & 31;
    int g4 = lane >> 2, tig = lane & 3;
    int wm = (w & 3) * 32;
    int wn = (w >> 2) * 64;

    const float* __restrict__ WT = g_WihT[dir];

    float acc[2][8][4];
    #pragma unroll
    for (int i = 0; i < 2; i++)
        #pragma unroll
        for (int j = 0; j < 8; j++)
            #pragma unroll
            for (int q = 0; q < 4; q++) acc[i][j][q] = 0.0f;

    // loader indices
    int alm = tid >> 1;              // A: m row
    int akq = (tid & 1) * 8;         // A: k start (8 floats)
    int blk = tid >> 4;              // B: k row
    int bln = (tid & 15) * 8;        // B: n start (8 floats)

    for (int kt = 0; kt < 19; kt++) {
        int k0 = kt * 16;
        // A tile: Xg[m0+m][k0..k0+15] -> Asm[k][m]
        {
            const float* src = g_Xg + (size_t)(m0 + alm) * KPAD + k0 + akq;
            float4 v0 = *reinterpret_cast<const float4*>(src);
            float4 v1 = *reinterpret_cast<const float4*>(src + 4);
            Asm[(akq + 0) * XP_ASTR + alm] = v0.x;
            Asm[(akq + 1) * XP_ASTR + alm] = v0.y;
            Asm[(akq + 2) * XP_ASTR + alm] = v0.z;
            Asm[(akq + 3) * XP_ASTR + alm] = v0.w;
            Asm[(akq + 4) * XP_ASTR + alm] = v1.x;
            Asm[(akq + 5) * XP_ASTR + alm] = v1.y;
            Asm[(akq + 6) * XP_ASTR + alm] = v1.z;
            Asm[(akq + 7) * XP_ASTR + alm] = v1.w;
        }
        // B tile: WT[k0+k][n0..n0+127] -> Bsm[k][n]
        {
            const float* src = WT + (size_t)(k0 + blk) * G4H + n0 + bln;
            float4 v0 = *reinterpret_cast<const float4*>(src);
            float4 v1 = *reinterpret_cast<const float4*>(src + 4);
            *reinterpret_cast<float4*>(Bsm + blk * XP_ASTR + bln) = v0;
            *reinterpret_cast<float4*>(Bsm + blk * XP_ASTR + bln + 4) = v1;
        }
        __syncthreads();
        #pragma unroll
        for (int kc = 0; kc < 2; kc++) {
            int kb = kc * 8;
            unsigned a[2][4];
            #pragma unroll
            for (int i = 0; i < 2; i++) {
                int m = wm + i * 16 + g4;
                a[i][0] = __float_as_uint(Asm[(kb + tig) * XP_ASTR + m]);
                a[i][1] = __float_as_uint(Asm[(kb + tig) * XP_ASTR + m + 8]);
                a[i][2] = __float_as_uint(Asm[(kb + tig + 4) * XP_ASTR + m]);
                a[i][3] = __float_as_uint(Asm[(kb + tig + 4) * XP_ASTR + m + 8]);
            }
            #pragma unroll
            for (int j = 0; j < 8; j++) {
                int n = wn + j * 8 + g4;
                unsigned b0 = __float_as_uint(Bsm[(kb + tig) * XP_ASTR + n]);
                unsigned b1 = __float_as_uint(Bsm[(kb + tig + 4) * XP_ASTR + n]);
                mma_tf32(acc[0][j], a[0][0], a[0][1], a[0][2], a[0][3], b0, b1);
                mma_tf32(acc[1][j], a[1][0], a[1][1], a[1][2], a[1][3], b0, b1);
            }
        }
        __syncthreads();
    }

    // stage C to smem as Csm[n][m], then write transposed output coalesced
    float* Csm = sm;  // [128][132]
    #pragma unroll
    for (int i = 0; i < 2; i++) {
        int m = wm + i * 16 + g4;
        #pragma unroll
        for (int j = 0; j < 8; j++) {
            int n = wn + j * 8 + 2 * tig;
            Csm[n * XP_ASTR + m] = acc[i][j][0];
            Csm[(n + 1) * XP_ASTR + m] = acc[i][j][1];
            Csm[n * XP_ASTR + m + 8] = acc[i][j][2];
            Csm[(n + 1) * XP_ASTR + m + 8] = acc[i][j][3];
        }
    }
    __syncthreads();

    int t = m0 >> 8;
    int b00 = m0 & 255;
    int n = tid >> 1;
    int mh = (tid & 1) * 64;
    float bv = g_bias[dir][n0 + n];
    float* dst = g_xpt[dir] + ((size_t)t * G4H + n0 + n) * BB + b00 + mh;
    #pragma unroll
    for (int v = 0; v < 16; v++) {
        float4 c = *reinterpret_cast<float4*>(Csm + n * XP_ASTR + mh + v * 4);
        c.x += bv; c.y += bv; c.z += bv; c.w += bv;
        *reinterpret_cast<float4*>(dst + v * 4) = c;
    }
}

// ---------------- persistent bidirectional LSTM recurrence ----------------
// grid 128 blocks x 128 threads. block: dir = bid>>6; idx=bid&63; bm=(idx>>4)*64; h0=(idx&15)*16.
// per step: C[64 x 64] = hprev[64 x 256] @ Whh_slice[256 x 64] (tf32 mma), + xproj, pointwise.
#define RC_ASTR 68
__global__ void lstm_persistent_kernel() {
    extern __shared__ float sm[];
    float* Wsm = sm;                     // [256][68]
    float* Asm = sm + 256 * RC_ASTR;     // [256][68], reused as Csm[64][68]
    int tid = threadIdx.x;
    int w = tid >> 5, lane = tid & 31;
    int g4 = lane >> 2, tig = lane & 3;
    int dir = blockIdx.x >> 6;
    int idx = blockIdx.x & 63;
    int bm = (idx >> 4) * 64;
    int h0 = (idx & 15) * 16;
    int wm = (w >> 1) * 32;
    int wn = (w & 1) * 32;

    // one-time: load Whh slice into smem. col c = g*16 + j -> global n = g*256 + h0 + j
    {
        const float* __restrict__ WT = g_WhhT[dir];
        for (int i = 0; i < 128; i++) {
            int v = tid + i * 128;
            int k = v >> 6, c = v & 63;
            Wsm[k * RC_ASTR + c] = WT[(size_t)k * G4H + (c >> 4) * HH + h0 + (c & 15)];
        }
    }
    __syncthreads();

    float creg[8];
    #pragma unroll
    for (int i = 0; i < 8; i++) creg[i] = 0.0f;

    const float* __restrict__ xpt = g_xpt[dir];
    float* __restrict__ h2 = g_h2[dir];
    float* __restrict__ hcur = g_hcur[dir];

    for (int s = 0; s < LL; s++) {
        int t = dir ? (LL - 1 - s) : s;
        float acc[2][4][4];
        #pragma unroll
        for (int i = 0; i < 2; i++)
            #pragma unroll
            for (int j = 0; j < 4; j++)
                #pragma unroll
                for (int q = 0; q < 4; q++) acc[i][j][q] = 0.0f;

        if (s > 0) {
            // load Asm[k][m] from hcur[k][bm+m]  (bypass L1: cross-SM data)
            #pragma unroll
            for (int i = 0; i < 32; i++) {
                int v = tid + i * 128;
                int k = v >> 4, m4 = (v & 15) * 4;
                float4 x = __ldcg(reinterpret_cast<const float4*>(hcur + k * BB + bm + m4));
                *reinterpret_cast<float4*>(Asm + k * RC_ASTR + m4) = x;
            }
            __syncthreads();
            #pragma unroll 4
            for (int kc = 0; kc < 32; kc++) {
                int kb = kc * 8;
                unsigned a[2][4];
                #pragma unroll
                for (int i = 0; i < 2; i++) {
                    int m = wm + i * 16 + g4;
                    a[i][0] = __float_as_uint(Asm[(kb + tig) * RC_ASTR + m]);
                    a[i][1] = __float_as_uint(Asm[(kb + tig) * RC_ASTR + m + 8]);
                    a[i][2] = __float_as_uint(Asm[(kb + tig + 4) * RC_ASTR + m]);
                    a[i][3] = __float_as_uint(Asm[(kb + tig + 4) * RC_ASTR + m + 8]);
                }
                #pragma unroll
                for (int j = 0; j < 4; j++) {
                    int n = wn + j * 8 + g4;
                    unsigned b0 = __float_as_uint(Wsm[(kb + tig) * RC_ASTR + n]);
                    unsigned b1 = __float_as_uint(Wsm[(kb + tig + 4) * RC_ASTR + n]);
                    mma_tf32(acc[0][j], a[0][0], a[0][1], a[0][2], a[0][3], b0, b1);
                    mma_tf32(acc[1][j], a[1][0], a[1][1], a[1][2], a[1][3], b0, b1);
                }
            }
            __syncthreads();  // done reading Asm before staging C into it
        }

        // stage C: Csm[c][m], c = gate*16 + hl
        float* Csm = Asm;
        #pragma unroll
        for (int i = 0; i < 2; i++) {
            int m = wm + i * 16 + g4;
            #pragma unroll
            for (int j = 0; j < 4; j++) {
                int n = wn + j * 8 + 2 * tig;
                Csm[n * RC_ASTR + m] = acc[i][j][0];
                Csm[(n + 1) * RC_ASTR + m] = acc[i][j][1];
                Csm[n * RC_ASTR + m + 8] = acc[i][j][2];
                Csm[(n + 1) * RC_ASTR + m + 8] = acc[i][j][3];
            }
        }
        __syncthreads();

        // pointwise LSTM: 1024 (b,h) pairs, 8 per thread, c state in registers
        #pragma unroll
        for (int q8 = 0; q8 < 8; q8++) {
            int q = tid + q8 * 128;
            int b = q & 63;
            int hl = q >> 6;
            size_t xb = ((size_t)t * G4H + h0 + hl) * BB + bm + b;
            float gi = Csm[hl * RC_ASTR + b]        + xpt[xb];
            float gf = Csm[(16 + hl) * RC_ASTR + b] + xpt[xb + (size_t)256 * BB];
            float gg = Csm[(32 + hl) * RC_ASTR + b] + xpt[xb + (size_t)512 * BB];
            float go = Csm[(48 + hl) * RC_ASTR + b] + xpt[xb + (size_t)768 * BB];
            float ig = sigmoidf_(gi);
            float fg = sigmoidf_(gf);
            float og = sigmoidf_(go);
            float cn = fg * creg[q8] + ig * tanhf(gg);
            float hn = og * tanhf(cn);
            creg[q8] = cn;
            h2[((size_t)t * HH + h0 + hl) * BB + bm + b] = hn;
            hcur[(h0 + hl) * BB + bm + b] = tf32r(hn);
        }

        // grid barrier
        __threadfence();
        __syncthreads();
        if (tid == 0) {
            atomicAdd(&g_count, 1u);
            unsigned target = 128u * (unsigned)(s + 1);
            volatile unsigned* p = &g_count;
            while (*p < target) { }
            __threadfence();
        }
        __syncthreads();
    }
}

// ---------------- emissions: em[t][b][tag] = sum_h h2[d][t][h][b] * lin_w[tag][d*H+h] + lin_b
// grid 256 (t), block 128 (b and b+128)
__global__ void emissions_kernel(const float* __restrict__ lin_w, const float* __restrict__ lin_b) {
    __shared__ float wst[H2 * TT];
    int t = blockIdx.x;
    int tid = threadIdx.x;
    for (int i = tid; i < H2 * TT; i += 128) {
        int h2i = i / TT, tg = i % TT;
        wst[i] = lin_w[tg * H2 + h2i];
    }
    __syncthreads();
    float acc0[TT], acc1[TT];
    #pragma unroll
    for (int tg = 0; tg < TT; tg++) {
        float bb = lin_b[tg];
        acc0[tg] = bb;
        acc1[tg] = bb;
    }
    #pragma unroll
    for (int d = 0; d < 2; d++) {
        const float* __restrict__ base = g_h2[d] + (size_t)t * HH * BB;
        for (int h = 0; h < HH; h++) {
            float x0 = base[h * BB + tid];
            float x1 = base[h * BB + tid + 128];
            const float* wr = wst + (d * HH + h) * TT;
            #pragma unroll
            for (int tg = 0; tg < TT; tg++) {
                acc0[tg] += x0 * wr[tg];
                acc1[tg] += x1 * wr[tg];
            }
        }
    }
    float* em0 = g_em + ((size_t)t * BB + tid) * TT;
    float* em1 = em0 + (size_t)128 * TT;
    #pragma unroll
    for (int tg = 0; tg < TT; tg++) {
        em0[tg] = acc0[tg];
        em1[tg] = acc1[tg];
    }
}

// ---------------- CRF gold-path score ----------------
__global__ void score_kernel(const int* __restrict__ tags, const int* __restrict__ mask_,
                             const float* __restrict__ start_trans, const float* __restrict__ end_trans,
                             const float* __restrict__ trans) {
    int warp = threadIdx.x >> 5, lane = threadIdx.x & 31;
    int b = blockIdx.x * 8 + warp;
    float sc = 0.0f;
    int mcount = 0;
    for (int t = lane; t < LL; t += 32) {
        int mk = mask_[t * BB + b];
        mcount += mk;
        if (t >= 1 && mk) {
            int tp = tags[(t - 1) * BB + b];
            int tt = tags[t * BB + b];
            sc += trans[tp * TT + tt] + g_em[((size_t)t * BB + b) * TT + tt];
        }
    }
    #pragma unroll
    for (int o = 16; o > 0; o >>= 1) {
        sc += __shfl_down_sync(0xffffffffu, sc, o);
        mcount += __shfl_down_sync(0xffffffffu, mcount, o);
    }
    if (lane == 0) {
        int t0 = tags[b];
        sc += start_trans[t0] + g_em[(size_t)b * TT + t0];
        int lt = tags[(mcount - 1) * BB + b];
        sc += end_trans[lt];
        g_score[b] = sc;
    }
}

// ---------------- CRF forward alpha recurrence ----------------
__global__ void alpha_kernel(const int* __restrict__ mask_,
                             const float* __restrict__ start_trans, const float* __restrict__ end_trans,
                             const float* __restrict__ trans) {
    int b = blockIdx.x;
    int j = threadIdx.x;
    __shared__ float tr[TT * TT];
    __shared__ float al[TT];
    for (int i = j; i < TT * TT; i += 32) tr[i] = trans[i];
    if (j < TT) al[j] = start_trans[j] + g_em[(size_t)b * TT + j];
    __syncwarp();
    for (int t = 1; t < LL; t++) {
        int mk = mask_[t * BB + b];
        float nxt = 0.0f;
        if (j < TT && mk) {
            float mx = -1e30f;
            #pragma unroll
            for (int i = 0; i < TT; i++) mx = fmaxf(mx, al[i] + tr[i * TT + j]);
            float sum = 0.0f;
            #pragma unroll
            for (int i = 0; i < TT; i++) sum += expf(al[i] + tr[i * TT + j] - mx);
            nxt = mx + logf(sum) + g_em[((size_t)t * BB + b) * TT + j];
        }
        __syncwarp();
        if (j < TT && mk) al[j] = nxt;
        __syncwarp();
    }
    if (j == 0) {
        float mx = -1e30f;
        for (int i = 0; i < TT; i++) mx = fmaxf(mx, al[i] + end_trans[i]);
        float sum = 0.0f;
        for (int i = 0; i < TT; i++) sum += expf(al[i] + end_trans[i] - mx);
        g_logZ[b] = mx + logf(sum);
    }
}

__global__ void final_kernel(float* __restrict__ out) {
    __shared__ float red[256];
    int b = threadIdx.x;
    red[b] = g_logZ[b] - g_score[b];
    __syncthreads();
    for (int s = 128; s > 0; s >>= 1) {
        if (b < s) red[b] += red[b + s];
        __syncthreads();
    }
    if (b == 0) out[0] = red[0];
}

// ---------------- launch ----------------
extern "C" void kernel_launch(void* const* d_in, const int* in_sizes, int n_in,
                              void* d_out, int out_size) {
    const int*   words       = (const int*)d_in[0];
    const int*   tags        = (const int*)d_in[1];
    const int*   mask        = (const int*)d_in[2];
    const float* embed_table = (const float*)d_in[3];
    const float* w_ih_f      = (const float*)d_in[4];
    const float* w_hh_f      = (const float*)d_in[5];
    const float* b_ih_f      = (const float*)d_in[6];
    const float* b_hh_f      = (const float*)d_in[7];
    const float* w_ih_b      = (const float*)d_in[8];
    const float* w_hh_b      = (const float*)d_in[9];
    const float* b_ih_b      = (const float*)d_in[10];
    const float* b_hh_b      = (const float*)d_in[11];
    const float* lin_w       = (const float*)d_in[12];
    const float* lin_b       = (const float*)d_in[13];
    const float* start_trans = (const float*)d_in[14];
    const float* end_trans   = (const float*)d_in[15];
    const float* trans       = (const float*)d_in[16];
    float* out = (float*)d_out;

    const int XP_SMEM = 128 * XP_ASTR * 4;      // 67584
    const int RC_SMEM = 2 * 256 * RC_ASTR * 4;  // 139264
    static bool attr_done = false;
    if (!attr_done) {
        cudaFuncSetAttribute(xproj_kernel, cudaFuncAttributeMaxDynamicSharedMemorySize, XP_SMEM);
        cudaFuncSetAttribute(lstm_persistent_kernel, cudaFuncAttributeMaxDynamicSharedMemorySize, RC_SMEM);
        attr_done = true;
    }

    prep_kernel<<<256, 256>>>(w_ih_f, w_hh_f, b_ih_f, b_hh_f,
                              w_ih_b, w_hh_b, b_ih_b, b_hh_b);
    gather_kernel<<<(MM * (KPAD / 4) + 255) / 256, 256>>>(words, embed_table);
    xproj_kernel<<<dim3(8, 512, 2), 256, XP_SMEM>>>();
    lstm_persistent_kernel<<<128, 128, RC_SMEM>>>();
    emissions_kernel<<<256, 128>>>(lin_w, lin_b);
    score_kernel<<<32, 256>>>(tags, mask, start_trans, end_trans, trans);
    alpha_kernel<<<256, 32>>>(mask, start_trans, end_trans, trans);
    final_kernel<<<1, 256>>>(out);
}

// round 5
// speedup vs baseline: 2.0922x; 1.5449x over previous
#include <cuda_runtime.h>
#include <math.h>

#define LL 256
#define BB 256
#define EE 300
#define KPAD 304
#define HH 256
#define TT 17
#define G4H 1024
#define H2 512
#define MM 65536

// ---------------- device scratch ----------------
__device__ float g_Xg[(size_t)MM * KPAD];            // gathered embeddings, tf32-rounded, padded
__device__ float g_WihT[2][KPAD * G4H];              // [k][n] tf32-rounded
__device__ float g_WhhT[2][HH * G4H];                // [k][n] tf32-rounded
__device__ float g_bias[2][G4H];
__device__ float g_xpt[2][(size_t)LL * G4H * BB];    // [dir][t][n][b] fp32
__device__ float g_h2[2][(size_t)LL * HH * BB];      // [dir][t][h][b] fp32
__device__ float g_hcur[2][2][HH * BB];              // [dir][parity][h][b] tf32-rounded
__device__ float g_em[(size_t)MM * TT];
__device__ float g_score[BB];
__device__ float g_logZ[BB];
__device__ unsigned g_cnt8[8];

__device__ __forceinline__ float tf32r(float x) {
    unsigned r;
    asm("cvt.rna.tf32.f32 %0, %1;" : "=r"(r) : "f"(x));
    return __uint_as_float(r);
}

__device__ __forceinline__ void mma_tf32(float* c, unsigned a0, unsigned a1, unsigned a2, unsigned a3,
                                         unsigned b0, unsigned b1) {
    asm volatile("mma.sync.aligned.m16n8k8.row.col.f32.tf32.tf32.f32 "
                 "{%0,%1,%2,%3},{%4,%5,%6,%7},{%8,%9},{%0,%1,%2,%3};"
                 : "+f"(c[0]), "+f"(c[1]), "+f"(c[2]), "+f"(c[3])
                 : "r"(a0), "r"(a1), "r"(a2), "r"(a3), "r"(b0), "r"(b1));
}

__device__ __forceinline__ float fsig(float x) {
    return __fdividef(1.0f, 1.0f + __expf(-x));
}
__device__ __forceinline__ float ftanh(float x) {
    return __fdividef(2.0f, 1.0f + __expf(-2.0f * x)) - 1.0f;
}

// ---------------- prep: transpose + tf32-round weights, biases, reset barriers ----------------
__global__ void prep_kernel(const float* __restrict__ w_ih_f, const float* __restrict__ w_hh_f,
                            const float* __restrict__ b_ih_f, const float* __restrict__ b_hh_f,
                            const float* __restrict__ w_ih_b, const float* __restrict__ w_hh_b,
                            const float* __restrict__ b_ih_b, const float* __restrict__ b_hh_b) {
    int idx = blockIdx.x * blockDim.x + threadIdx.x;
    int stride = gridDim.x * blockDim.x;
    if (idx < 8) g_cnt8[idx] = 0u;
    for (int i = idx; i < KPAD * G4H; i += stride) {
        int k = i / G4H, n = i % G4H;
        g_WihT[0][i] = (k < EE) ? tf32r(w_ih_f[n * EE + k]) : 0.0f;
        g_WihT[1][i] = (k < EE) ? tf32r(w_ih_b[n * EE + k]) : 0.0f;
    }
    for (int i = idx; i < HH * G4H; i += stride) {
        int k = i / G4H, n = i % G4H;
        g_WhhT[0][i] = tf32r(w_hh_f[n * HH + k]);
        g_WhhT[1][i] = tf32r(w_hh_b[n * HH + k]);
    }
    for (int i = idx; i < G4H; i += stride) {
        g_bias[0][i] = b_ih_f[i] + b_hh_f[i];
        g_bias[1][i] = b_ih_b[i] + b_hh_b[i];
    }
}

// ---------------- embedding gather + tf32 round + pad ----------------
__global__ void gather_kernel(const int* __restrict__ words, const float* __restrict__ embed) {
    int idx = blockIdx.x * blockDim.x + threadIdx.x;
    const int total = MM * (KPAD / 4);
    if (idx >= total) return;
    int m = idx / (KPAD / 4);
    int c4 = idx % (KPAD / 4);
    int k = c4 * 4;
    const float* row = embed + (size_t)words[m] * EE;
    float4 v;
    v.x = (k + 0 < EE) ? tf32r(row[k + 0]) : 0.0f;
    v.y = (k + 1 < EE) ? tf32r(row[k + 1]) : 0.0f;
    v.z = (k + 2 < EE) ? tf32r(row[k + 2]) : 0.0f;
    v.w = (k + 3 < EE) ? tf32r(row[k + 3]) : 0.0f;
    *reinterpret_cast<float4*>(g_Xg + (size_t)m * KPAD + k) = v;
}

// ---------------- xproj: tf32 mma GEMM (unchanged from round-3 passing kernel) ----------------
#define XP_ASTR 132
__global__ void xproj_kernel() {
    extern __shared__ float sm[];
    float* Asm = sm;
    float* Bsm = sm + 16 * XP_ASTR;
    int dir = blockIdx.z;
    int n0 = blockIdx.x * 128;
    int m0 = blockIdx.y * 128;
    int tid = threadIdx.x;
    int w = tid >> 5, lane = tid & 31;
    int g4 = lane >> 2, tig = lane & 3;
    int wm = (w & 3) * 32;
    int wn = (w >> 2) * 64;

    const float* __restrict__ WT = g_WihT[dir];

    float acc[2][8][4];
    #pragma unroll
    for (int i = 0; i < 2; i++)
        #pragma unroll
        for (int j = 0; j < 8; j++)
            #pragma unroll
            for (int q = 0; q < 4; q++) acc[i][j][q] = 0.0f;

    int alm = tid >> 1;
    int akq = (tid & 1) * 8;
    int blk = tid >> 4;
    int bln = (tid & 15) * 8;

    for (int kt = 0; kt < 19; kt++) {
        int k0 = kt * 16;
        {
            const float* src = g_Xg + (size_t)(m0 + alm) * KPAD + k0 + akq;
            float4 v0 = *reinterpret_cast<const float4*>(src);
            float4 v1 = *reinterpret_cast<const float4*>(src + 4);
            Asm[(akq + 0) * XP_ASTR + alm] = v0.x;
            Asm[(akq + 1) * XP_ASTR + alm] = v0.y;
            Asm[(akq + 2) * XP_ASTR + alm] = v0.z;
            Asm[(akq + 3) * XP_ASTR + alm] = v0.w;
            Asm[(akq + 4) * XP_ASTR + alm] = v1.x;
            Asm[(akq + 5) * XP_ASTR + alm] = v1.y;
            Asm[(akq + 6) * XP_ASTR + alm] = v1.z;
            Asm[(akq + 7) * XP_ASTR + alm] = v1.w;
        }
        {
            const float* src = WT + (size_t)(k0 + blk) * G4H + n0 + bln;
            float4 v0 = *reinterpret_cast<const float4*>(src);
            float4 v1 = *reinterpret_cast<const float4*>(src + 4);
            *reinterpret_cast<float4*>(Bsm + blk * XP_ASTR + bln) = v0;
            *reinterpret_cast<float4*>(Bsm + blk * XP_ASTR + bln + 4) = v1;
        }
        __syncthreads();
        #pragma unroll
        for (int kc = 0; kc < 2; kc++) {
            int kb = kc * 8;
            unsigned a[2][4];
            #pragma unroll
            for (int i = 0; i < 2; i++) {
                int m = wm + i * 16 + g4;
                a[i][0] = __float_as_uint(Asm[(kb + tig) * XP_ASTR + m]);
                a[i][1] = __float_as_uint(Asm[(kb + tig) * XP_ASTR + m + 8]);
                a[i][2] = __float_as_uint(Asm[(kb + tig + 4) * XP_ASTR + m]);
                a[i][3] = __float_as_uint(Asm[(kb + tig + 4) * XP_ASTR + m + 8]);
            }
            #pragma unroll
            for (int j = 0; j < 8; j++) {
                int n = wn + j * 8 + g4;
                unsigned b0 = __float_as_uint(Bsm[(kb + tig) * XP_ASTR + n]);
                unsigned b1 = __float_as_uint(Bsm[(kb + tig + 4) * XP_ASTR + n]);
                mma_tf32(acc[0][j], a[0][0], a[0][1], a[0][2], a[0][3], b0, b1);
                mma_tf32(acc[1][j], a[1][0], a[1][1], a[1][2], a[1][3], b0, b1);
            }
        }
        __syncthreads();
    }

    float* Csm = sm;
    #pragma unroll
    for (int i = 0; i < 2; i++) {
        int m = wm + i * 16 + g4;
        #pragma unroll
        for (int j = 0; j < 8; j++) {
            int n = wn + j * 8 + 2 * tig;
            Csm[n * XP_ASTR + m] = acc[i][j][0];
            Csm[(n + 1) * XP_ASTR + m] = acc[i][j][1];
            Csm[n * XP_ASTR + m + 8] = acc[i][j][2];
            Csm[(n + 1) * XP_ASTR + m + 8] = acc[i][j][3];
        }
    }
    __syncthreads();

    int t = m0 >> 8;
    int b00 = m0 & 255;
    int n = tid >> 1;
    int mh = (tid & 1) * 64;
    float bv = g_bias[dir][n0 + n];
    float* dst = g_xpt[dir] + ((size_t)t * G4H + n0 + n) * BB + b00 + mh;
    #pragma unroll
    for (int v = 0; v < 16; v++) {
        float4 c = *reinterpret_cast<float4*>(Csm + n * XP_ASTR + mh + v * 4);
        c.x += bv; c.y += bv; c.z += bv; c.w += bv;
        *reinterpret_cast<float4*>(dst + v * 4) = c;
    }
}

// ---------------- persistent bidirectional LSTM recurrence (mma.sync tf32) ----------------
// grid 128 x 128 thr. dir = bid>>6; idx=bid&63; bm=(idx>>4)*64; h0=(idx&15)*16.
// Barrier group = (dir, bm) -> 16 CTAs, 8 independent groups.
#define RC_ASTR 68
__global__ void lstm_persistent_kernel() {
    extern __shared__ float sm[];
    float* Wsm = sm;                     // [256][68]
    float* Asm = sm + 256 * RC_ASTR;     // [256][68], reused as Csm[64][68]
    int tid = threadIdx.x;
    int w = tid >> 5, lane = tid & 31;
    int g4 = lane >> 2, tig = lane & 3;
    int dir = blockIdx.x >> 6;
    int idx = blockIdx.x & 63;
    int mt = idx >> 4;
    int bm = mt * 64;
    int h0 = (idx & 15) * 16;
    int grp = dir * 4 + mt;
    int wm = (w >> 1) * 32;
    int wn = (w & 1) * 32;

    // one-time: load Whh slice into smem. col c = g*16+j -> global n = g*256 + h0 + j
    {
        const float* __restrict__ WT = g_WhhT[dir];
        for (int i = 0; i < 128; i++) {
            int v = tid + i * 128;
            int k = v >> 6, c = v & 63;
            Wsm[k * RC_ASTR + c] = WT[(size_t)k * G4H + (c >> 4) * HH + h0 + (c & 15)];
        }
    }
    __syncthreads();

    float creg[8];
    #pragma unroll
    for (int i = 0; i < 8; i++) creg[i] = 0.0f;

    const float* __restrict__ xpt = g_xpt[dir];
    float* __restrict__ h2 = g_h2[dir];

    // pointwise mapping: this thread handles b = bm + (tid&63), hl = (tid>>6) + 2*q8
    int pb = tid & 63;
    int ph0 = tid >> 6;

    for (int s = 0; s < LL; s++) {
        int t = dir ? (LL - 1 - s) : s;

        // prefetch xpt for this step (independent of barrier) : 8 (b,h) pairs x 4 gates
        float xg[8][4];
        {
            const float* xb = xpt + ((size_t)t * G4H + h0) * BB + bm + pb;
            #pragma unroll
            for (int q8 = 0; q8 < 8; q8++) {
                int hl = ph0 + q8 * 2;
                #pragma unroll
                for (int g = 0; g < 4; g++)
                    xg[q8][g] = __ldcg(xb + (size_t)(g * 256 + hl) * BB);
            }
        }

        float acc[2][4][4];
        #pragma unroll
        for (int i = 0; i < 2; i++)
            #pragma unroll
            for (int j = 0; j < 4; j++)
                #pragma unroll
                for (int q = 0; q < 4; q++) acc[i][j][q] = 0.0f;

        if (s > 0) {
            // load Asm[k][m] from hcur[read parity][k][bm+m]
            const float* __restrict__ hr = g_hcur[dir][(s & 1) ^ 1];
            #pragma unroll
            for (int i = 0; i < 32; i++) {
                int v = tid + i * 128;
                int k = v >> 4, m4 = (v & 15) * 4;
                float4 x = __ldcg(reinterpret_cast<const float4*>(hr + k * BB + bm + m4));
                *reinterpret_cast<float4*>(Asm + k * RC_ASTR + m4) = x;
            }
            __syncthreads();
            #pragma unroll 4
            for (int kc = 0; kc < 32; kc++) {
                int kb = kc * 8;
                unsigned a[2][4];
                #pragma unroll
                for (int i = 0; i < 2; i++) {
                    int m = wm + i * 16 + g4;
                    a[i][0] = __float_as_uint(Asm[(kb + tig) * RC_ASTR + m]);
                    a[i][1] = __float_as_uint(Asm[(kb + tig) * RC_ASTR + m + 8]);
                    a[i][2] = __float_as_uint(Asm[(kb + tig + 4) * RC_ASTR + m]);
                    a[i][3] = __float_as_uint(Asm[(kb + tig + 4) * RC_ASTR + m + 8]);
                }
                #pragma unroll
                for (int j = 0; j < 4; j++) {
                    int n = wn + j * 8 + g4;
                    unsigned b0 = __float_as_uint(Wsm[(kb + tig) * RC_ASTR + n]);
                    unsigned b1 = __float_as_uint(Wsm[(kb + tig + 4) * RC_ASTR + n]);
                    mma_tf32(acc[0][j], a[0][0], a[0][1], a[0][2], a[0][3], b0, b1);
                    mma_tf32(acc[1][j], a[1][0], a[1][1], a[1][2], a[1][3], b0, b1);
                }
            }
            __syncthreads();  // done reading Asm before staging C into it
        }

        // stage C: Csm[c][m], c = gate*16 + hl
        float* Csm = Asm;
        #pragma unroll
        for (int i = 0; i < 2; i++) {
            int m = wm + i * 16 + g4;
            #pragma unroll
            for (int j = 0; j < 4; j++) {
                int n = wn + j * 8 + 2 * tig;
                Csm[n * RC_ASTR + m] = acc[i][j][0];
                Csm[(n + 1) * RC_ASTR + m] = acc[i][j][1];
                Csm[n * RC_ASTR + m + 8] = acc[i][j][2];
                Csm[(n + 1) * RC_ASTR + m + 8] = acc[i][j][3];
            }
        }
        __syncthreads();

        // pointwise LSTM, c state in registers; write h to parity buffer
        float* __restrict__ hw = g_hcur[dir][s & 1];
        #pragma unroll
        for (int q8 = 0; q8 < 8; q8++) {
            int hl = ph0 + q8 * 2;
            float gi = Csm[hl * RC_ASTR + pb]        + xg[q8][0];
            float gf = Csm[(16 + hl) * RC_ASTR + pb] + xg[q8][1];
            float gg = Csm[(32 + hl) * RC_ASTR + pb] + xg[q8][2];
            float go = Csm[(48 + hl) * RC_ASTR + pb] + xg[q8][3];
            float ig = fsig(gi);
            float fg = fsig(gf);
            float og = fsig(go);
            float cn = fg * creg[q8] + ig * ftanh(gg);
            float hn = og * ftanh(cn);
            creg[q8] = cn;
            int b = bm + pb;
            int h = h0 + hl;
            h2[((size_t)t * HH + h) * BB + b] = hn;
            hw[h * BB + b] = tf32r(hn);
        }

        // group barrier: 16 CTAs sharing (dir, bm)
        __threadfence();
        __syncthreads();
        if (tid == 0) {
            unsigned tgt = 16u * (unsigned)(s + 1);
            atomicAdd(&g_cnt8[grp], 1u);
            volatile unsigned* p = &g_cnt8[grp];
            while (*p < tgt) { }
            __threadfence();
        }
        __syncthreads();
    }
}

// ---------------- emissions ----------------
__global__ void emissions_kernel(const float* __restrict__ lin_w, const float* __restrict__ lin_b) {
    __shared__ float wst[H2 * TT];
    int t = blockIdx.x;
    int tid = threadIdx.x;
    for (int i = tid; i < H2 * TT; i += 128) {
        int h2i = i / TT, tg = i % TT;
        wst[i] = lin_w[tg * H2 + h2i];
    }
    __syncthreads();
    float acc0[TT], acc1[TT];
    #pragma unroll
    for (int tg = 0; tg < TT; tg++) {
        float bb = lin_b[tg];
        acc0[tg] = bb;
        acc1[tg] = bb;
    }
    #pragma unroll
    for (int d = 0; d < 2; d++) {
        const float* __restrict__ base = g_h2[d] + (size_t)t * HH * BB;
        for (int h = 0; h < HH; h++) {
            float x0 = base[h * BB + tid];
            float x1 = base[h * BB + tid + 128];
            const float* wr = wst + (d * HH + h) * TT;
            #pragma unroll
            for (int tg = 0; tg < TT; tg++) {
                acc0[tg] += x0 * wr[tg];
                acc1[tg] += x1 * wr[tg];
            }
        }
    }
    float* em0 = g_em + ((size_t)t * BB + tid) * TT;
    float* em1 = em0 + (size_t)128 * TT;
    #pragma unroll
    for (int tg = 0; tg < TT; tg++) {
        em0[tg] = acc0[tg];
        em1[tg] = acc1[tg];
    }
}

// ---------------- CRF gold-path score ----------------
__global__ void score_kernel(const int* __restrict__ tags, const int* __restrict__ mask_,
                             const float* __restrict__ start_trans, const float* __restrict__ end_trans,
                             const float* __restrict__ trans) {
    int warp = threadIdx.x >> 5, lane = threadIdx.x & 31;
    int b = blockIdx.x * 8 + warp;
    float sc = 0.0f;
    int mcount = 0;
    for (int t = lane; t < LL; t += 32) {
        int mk = mask_[t * BB + b];
        mcount += mk;
        if (t >= 1 && mk) {
            int tp = tags[(t - 1) * BB + b];
            int tt = tags[t * BB + b];
            sc += trans[tp * TT + tt] + g_em[((size_t)t * BB + b) * TT + tt];
        }
    }
    #pragma unroll
    for (int o = 16; o > 0; o >>= 1) {
        sc += __shfl_down_sync(0xffffffffu, sc, o);
        mcount += __shfl_down_sync(0xffffffffu, mcount, o);
    }
    if (lane == 0) {
        int t0 = tags[b];
        sc += start_trans[t0] + g_em[(size_t)b * TT + t0];
        int lt = tags[(mcount - 1) * BB + b];
        sc += end_trans[lt];
        g_score[b] = sc;
    }
}

// ---------------- CRF forward alpha recurrence ----------------
__global__ void alpha_kernel(const int* __restrict__ mask_,
                             const float* __restrict__ start_trans, const float* __restrict__ end_trans,
                             const float* __restrict__ trans) {
    int b = blockIdx.x;
    int j = threadIdx.x;
    __shared__ float tr[TT * TT];
    __shared__ float al[TT];
    for (int i = j; i < TT * TT; i += 32) tr[i] = trans[i];
    if (j < TT) al[j] = start_trans[j] + g_em[(size_t)b * TT + j];
    __syncwarp();
    for (int t = 1; t < LL; t++) {
        int mk = mask_[t * BB + b];
        float nxt = 0.0f;
        if (j < TT && mk) {
            float mx = -1e30f;
            #pragma unroll
            for (int i = 0; i < TT; i++) mx = fmaxf(mx, al[i] + tr[i * TT + j]);
            float sum = 0.0f;
            #pragma unroll
            for (int i = 0; i < TT; i++) sum += expf(al[i] + tr[i * TT + j] - mx);
            nxt = mx + logf(sum) + g_em[((size_t)t * BB + b) * TT + j];
        }
        __syncwarp();
        if (j < TT && mk) al[j] = nxt;
        __syncwarp();
    }
    if (j == 0) {
        float mx = -1e30f;
        for (int i = 0; i < TT; i++) mx = fmaxf(mx, al[i] + end_trans[i]);
        float sum = 0.0f;
        for (int i = 0; i < TT; i++) sum += expf(al[i] + end_trans[i] - mx);
        g_logZ[b] = mx + logf(sum);
    }
}

__global__ void final_kernel(float* __restrict__ out) {
    __shared__ float red[256];
    int b = threadIdx.x;
    red[b] = g_logZ[b] - g_score[b];
    __syncthreads();
    for (int s = 128; s > 0; s >>= 1) {
        if (b < s) red[b] += red[b + s];
        __syncthreads();
    }
    if (b == 0) out[0] = red[0];
}

// ---------------- launch ----------------
extern "C" void kernel_launch(void* const* d_in, const int* in_sizes, int n_in,
                              void* d_out, int out_size) {
    const int*   words       = (const int*)d_in[0];
    const int*   tags        = (const int*)d_in[1];
    const int*   mask        = (const int*)d_in[2];
    const float* embed_table = (const float*)d_in[3];
    const float* w_ih_f      = (const float*)d_in[4];
    const float* w_hh_f      = (const float*)d_in[5];
    const float* b_ih_f      = (const float*)d_in[6];
    const float* b_hh_f      = (const float*)d_in[7];
    const float* w_ih_b      = (const float*)d_in[8];
    const float* w_hh_b      = (const float*)d_in[9];
    const float* b_ih_b      = (const float*)d_in[10];
    const float* b_hh_b      = (const float*)d_in[11];
    const float* lin_w       = (const float*)d_in[12];
    const float* lin_b       = (const float*)d_in[13];
    const float* start_trans = (const float*)d_in[14];
    const float* end_trans   = (const float*)d_in[15];
    const float* trans       = (const float*)d_in[16];
    float* out = (float*)d_out;

    const int XP_SMEM = 128 * XP_ASTR * 4;      // 67584
    const int RC_SMEM = 2 * 256 * RC_ASTR * 4;  // 139264
    static bool attr_done = false;
    if (!attr_done) {
        cudaFuncSetAttribute(xproj_kernel, cudaFuncAttributeMaxDynamicSharedMemorySize, XP_SMEM);
        cudaFuncSetAttribute(lstm_persistent_kernel, cudaFuncAttributeMaxDynamicSharedMemorySize, RC_SMEM);
        attr_done = true;
    }

    prep_kernel<<<256, 256>>>(w_ih_f, w_hh_f, b_ih_f, b_hh_f,
                              w_ih_b, w_hh_b, b_ih_b, b_hh_b);
    gather_kernel<<<(MM * (KPAD / 4) + 255) / 256, 256>>>(words, embed_table);
    xproj_kernel<<<dim3(8, 512, 2), 256, XP_SMEM>>>();
    lstm_persistent_kernel<<<128, 128, RC_SMEM>>>();
    emissions_kernel<<<256, 128>>>(lin_w, lin_b);
    score_kernel<<<32, 256>>>(tags, mask, start_trans, end_trans, trans);
    alpha_kernel<<<256, 32>>>(mask, start_trans, end_trans, trans);
    final_kernel<<<1, 256>>>(out);
}